// round 11
// baseline (speedup 1.0000x reference)
#include <cuda_runtime.h>
#include <cuda_bf16.h>
#include <cstdint>

#define BB 8
#define TT 2048
#define DD 1024
#define MT (BB * TT)   // 16384 rows

// ---------------- scratch (__device__ globals; no allocs allowed) -----------
__device__ float g_q[(size_t)MT * DD];
__device__ float g_k[(size_t)MT * DD];
__device__ float g_v[(size_t)MT * DD];
__device__ __nv_bfloat16 g_xhi[(size_t)MT * DD];
__device__ __nv_bfloat16 g_xlo[(size_t)MT * DD];
__device__ __nv_bfloat16 g_whi[3][(size_t)DD * DD];   // stacked q,k,v -> rows 0..3071
__device__ __nv_bfloat16 g_wlo[3][(size_t)DD * DD];
// scan intermediates
#define NCH 64
#define LCH 32
__device__ float g_finals[NCH * BB * DD];
__device__ float g_carries[NCH * BB * DD];

// ---------------- helpers ----------------------------------------------------
__device__ __forceinline__ uint32_t smem_to_u32(const void* p) {
    uint32_t a;
    asm("{ .reg .u64 t; cvta.to.shared.u64 t, %1; cvt.u32.u64 %0, t; }"
        : "=r"(a) : "l"(p));
    return a;
}
__device__ __forceinline__ void cp_async16(uint32_t saddr, const void* gptr) {
    asm volatile("cp.async.cg.shared.global [%0], [%1], 16;\n"
                 :: "r"(saddr), "l"(gptr));
}
__device__ __forceinline__ void cp_commit() {
    asm volatile("cp.async.commit_group;\n" ::: "memory");
}
__device__ __forceinline__ void cp_wait1() {
    asm volatile("cp.async.wait_group 1;\n" ::: "memory");
}
__device__ __forceinline__ void cp_wait0() {
    asm volatile("cp.async.wait_group 0;\n" ::: "memory");
}
__device__ __forceinline__ void ldm_x4(uint32_t* r, uint32_t addr) {
    asm volatile("ldmatrix.sync.aligned.m8n8.x4.shared.b16 {%0,%1,%2,%3}, [%4];"
                 : "=r"(r[0]), "=r"(r[1]), "=r"(r[2]), "=r"(r[3]) : "r"(addr));
}
__device__ __forceinline__ void mma_bf16(float* c, const uint32_t* a, const uint32_t* b) {
    asm volatile("mma.sync.aligned.m16n8k16.row.col.f32.bf16.bf16.f32 "
                 "{%0,%1,%2,%3}, {%4,%5,%6,%7}, {%8,%9}, {%0,%1,%2,%3};"
                 : "+f"(c[0]), "+f"(c[1]), "+f"(c[2]), "+f"(c[3])
                 : "r"(a[0]), "r"(a[1]), "r"(a[2]), "r"(a[3]),
                   "r"(b[0]), "r"(b[1]));
}

// ---------------- split fp32 -> bf16 hi/lo (grid-stride, MLP=4) --------------
__global__ __launch_bounds__(256) void split_kernel(const float* __restrict__ src,
                                                    __nv_bfloat16* __restrict__ hi,
                                                    __nv_bfloat16* __restrict__ lo,
                                                    int n4) {
    const int stride = gridDim.x * blockDim.x;
    int i = blockIdx.x * blockDim.x + threadIdx.x;
    float4 v[4];
    int idx[4];
#pragma unroll
    for (int r = 0; r < 4; r++, i += stride) {
        idx[r] = (i < n4) ? i : (n4 - 1);
        v[r] = ((const float4*)src)[idx[r]];
    }
#pragma unroll
    for (int r = 0; r < 4; r++) {
        __nv_bfloat16 h[4], l[4];
        float f[4] = {v[r].x, v[r].y, v[r].z, v[r].w};
#pragma unroll
        for (int j = 0; j < 4; j++) {
            h[j] = __float2bfloat16_rn(f[j]);
            l[j] = __float2bfloat16_rn(f[j] - __bfloat162float(h[j]));
        }
        ((uint2*)hi)[idx[r]] = *(uint2*)h;
        ((uint2*)lo)[idx[r]] = *(uint2*)l;
    }
}

// ---------------- fused QKV HMMA bf16 split GEMM (unchanged, passing) --------
#define ASTR 40                    // padded row stride in bf16 elements
#define ROWB (ASTR * 2)            // 80 bytes
#define ST_A_HI 0
#define ST_A_LO (128 * ROWB)               // 10240
#define ST_B_HI (2 * 128 * ROWB)           // 20480
#define ST_B_LO (ST_B_HI + 256 * ROWB)     // 40960
#define STAGE_B (ST_B_LO + 256 * ROWB)     // 61440
#define NSTAGE 3
#define NCHK (DD / 32)             // 32 chunks

__global__ __launch_bounds__(256, 1) void gemm_qkv_kernel(
    const __nv_bfloat16* __restrict__ Ahi, const __nv_bfloat16* __restrict__ Alo,
    const __nv_bfloat16* __restrict__ Whi, const __nv_bfloat16* __restrict__ Wlo,
    const float* __restrict__ bq, const float* __restrict__ bk,
    const float* __restrict__ bv,
    float* __restrict__ Cq, float* __restrict__ Ck, float* __restrict__ Cv) {
    extern __shared__ char smem[];
    const uint32_t smem_base = smem_to_u32(smem);
    const int tid = threadIdx.x;
    const int wid = tid >> 5;
    const int lane = tid & 31;
    const int warp_m = wid & 1;          // 2 warps in M (64 rows each)
    const int warp_n = wid >> 1;         // 4 warps in N (64 cols each)
    const int bm = blockIdx.y * 128;
    const int bn = blockIdx.x * 256;     // 0..3071 within stacked W
    const int seg = bn >> 10;            // 0=q, 1=k, 2=v
    const int cn = bn & (DD - 1);        // column base within segment

    const float* bias = (seg == 0) ? bq : (seg == 1) ? bk : bv;
    float* C = (seg == 0) ? Cq : (seg == 1) ? Ck : Cv;

    const int lr = lane & 7;
    const int g = lane >> 3;                       // 0..3
    const uint32_t a_row = warp_m * 64 + (g & 1) * 8 + lr;   // + mt*16
    const uint32_t a_koff = (g >> 1) * 8;
    const uint32_t b_row = warp_n * 64 + ((lane >> 4) << 3) + lr;  // + j*16
    const uint32_t b_koff = ((lane >> 3) & 1) * 8;

    float acc[4][8][4];
#pragma unroll
    for (int i = 0; i < 4; i++)
#pragma unroll
        for (int j = 0; j < 8; j++)
#pragma unroll
            for (int r = 0; r < 4; r++) acc[i][j][r] = 0.f;

    auto issue_load = [&](int ch) {
        const uint32_t sbase = smem_base + (ch % NSTAGE) * STAGE_B;
        const int k0 = ch * 32;
        {
            const __nv_bfloat16* sh = Ahi + (size_t)bm * DD + k0;
            const __nv_bfloat16* sl = Alo + (size_t)bm * DD + k0;
#pragma unroll
            for (int rep = 0; rep < 2; rep++) {
                const int idx = tid + rep * 256;        // 0..511
                const int r = idx >> 2, segi = idx & 3;
                cp_async16(sbase + ST_A_HI + r * ROWB + segi * 16,
                           sh + (size_t)r * DD + segi * 8);
                cp_async16(sbase + ST_A_LO + r * ROWB + segi * 16,
                           sl + (size_t)r * DD + segi * 8);
            }
        }
        {
            const __nv_bfloat16* sh = Whi + (size_t)bn * DD + k0;
            const __nv_bfloat16* sl = Wlo + (size_t)bn * DD + k0;
#pragma unroll
            for (int rep = 0; rep < 4; rep++) {
                const int idx = tid + rep * 256;        // 0..1023
                const int r = idx >> 2, segi = idx & 3;
                cp_async16(sbase + ST_B_HI + r * ROWB + segi * 16,
                           sh + (size_t)r * DD + segi * 8);
                cp_async16(sbase + ST_B_LO + r * ROWB + segi * 16,
                           sl + (size_t)r * DD + segi * 8);
            }
        }
        cp_commit();
    };

    issue_load(0);
    issue_load(1);

    for (int ch = 0; ch < NCHK; ch++) {
        if (ch == NCHK - 1) cp_wait0(); else cp_wait1();
        __syncthreads();
        if (ch + 2 < NCHK) issue_load(ch + 2);

        const uint32_t base = smem_base + (ch % NSTAGE) * STAGE_B;
#pragma unroll
        for (int ks = 0; ks < 2; ks++) {
            uint32_t ahi[4][4], alo[4][4], bhi[4][4], blo[4][4];
#pragma unroll
            for (int mt = 0; mt < 4; mt++) {
                uint32_t ar = base + (a_row + mt * 16) * ROWB
                            + (ks * 16 + a_koff) * 2;
                ldm_x4(ahi[mt], ar + ST_A_HI);
                ldm_x4(alo[mt], ar + ST_A_LO);
            }
#pragma unroll
            for (int j = 0; j < 4; j++) {             // each covers 2 n-tiles
                uint32_t br = base + (b_row + j * 16) * ROWB
                            + (ks * 16 + b_koff) * 2;
                ldm_x4(bhi[j], br + ST_B_HI);
                ldm_x4(blo[j], br + ST_B_LO);
            }
#pragma unroll
            for (int mt = 0; mt < 4; mt++)
#pragma unroll
                for (int nt = 0; nt < 8; nt++)
                    mma_bf16(acc[mt][nt], ahi[mt], &bhi[nt >> 1][(nt & 1) * 2]);
#pragma unroll
            for (int mt = 0; mt < 4; mt++)
#pragma unroll
                for (int nt = 0; nt < 8; nt++)
                    mma_bf16(acc[mt][nt], ahi[mt], &blo[nt >> 1][(nt & 1) * 2]);
#pragma unroll
            for (int mt = 0; mt < 4; mt++)
#pragma unroll
                for (int nt = 0; nt < 8; nt++)
                    mma_bf16(acc[mt][nt], alo[mt], &bhi[nt >> 1][(nt & 1) * 2]);
        }
    }

    const int qr = lane >> 2;           // 0..7
    const int qc = (lane & 3) * 2;      // 0,2,4,6
#pragma unroll
    for (int mt = 0; mt < 4; mt++) {
#pragma unroll
        for (int nt = 0; nt < 8; nt++) {
            const int row0 = bm + warp_m * 64 + mt * 16 + qr;
            const int col = cn + warp_n * 64 + nt * 8 + qc;
            const float2 bvv = *(const float2*)&bias[col];
            float2 v0, v1;
            v0.x = acc[mt][nt][0] + bvv.x;
            v0.y = acc[mt][nt][1] + bvv.y;
            v1.x = acc[mt][nt][2] + bvv.x;
            v1.y = acc[mt][nt][3] + bvv.y;
            *(float2*)&C[(size_t)row0 * DD + col] = v0;
            *(float2*)&C[(size_t)(row0 + 8) * DD + col] = v1;
        }
    }
}

// ---------------- chunked scan, float4-vectorized ----------------------------
#define D4 (DD / 4)    // 256 float4 groups per row

// pass1: per (b, chunk, d4) local scan of kv over LCH steps -> finals
__global__ __launch_bounds__(256) void scan1_kernel(const float* __restrict__ decay) {
    int x = blockIdx.x * blockDim.x + threadIdx.x;   // < NCH*BB*D4
    int d4 = x & (D4 - 1);
    int b = (x >> 8) & (BB - 1);
    int c = x >> 11;
    float4 dec = ((const float4*)decay)[d4];
    const float4* K4 = (const float4*)g_k;
    const float4* V4 = (const float4*)g_v;
    size_t base = ((size_t)b * TT + (size_t)c * LCH) * D4 + d4;
    float4 mem = make_float4(0.f, 0.f, 0.f, 0.f);
#pragma unroll 4
    for (int t = 0; t < LCH; t++) {
        float4 kk = K4[base + (size_t)t * D4];
        float4 vv = V4[base + (size_t)t * D4];
        mem.x = fmaf(dec.x, mem.x, kk.x * vv.x);
        mem.y = fmaf(dec.y, mem.y, kk.y * vv.y);
        mem.z = fmaf(dec.z, mem.z, kk.z * vv.z);
        mem.w = fmaf(dec.w, mem.w, kk.w * vv.w);
    }
    ((float4*)g_finals)[((size_t)c * BB + b) * D4 + d4] = mem;
}

// pass2: per (b, d4) combine carries across chunks
__global__ __launch_bounds__(256) void scan2_kernel(const float* __restrict__ decay) {
    int x = blockIdx.x * blockDim.x + threadIdx.x;   // < BB*D4
    int d4 = x & (D4 - 1);
    int b = x >> 8;
    float4 dec = ((const float4*)decay)[d4];
    float4 pL = dec;
#pragma unroll
    for (int i = 0; i < 5; i++) {                    // dec^32
        pL.x *= pL.x; pL.y *= pL.y; pL.z *= pL.z; pL.w *= pL.w;
    }
    float4 carry = make_float4(0.f, 0.f, 0.f, 0.f);
    const float4* F4 = (const float4*)g_finals;
    float4* C4 = (float4*)g_carries;
#pragma unroll
    for (int c = 0; c < NCH; c++) {
        size_t idx = ((size_t)c * BB + b) * D4 + d4;
        C4[idx] = carry;
        float4 f = F4[idx];
        carry.x = fmaf(pL.x, carry.x, f.x);
        carry.y = fmaf(pL.y, carry.y, f.y);
        carry.z = fmaf(pL.z, carry.z, f.z);
        carry.w = fmaf(pL.w, carry.w, f.w);
    }
}

// pass3: full scan with carry-in, emit out = q * mem
__global__ __launch_bounds__(256) void scan3_kernel(const float* __restrict__ decay,
                                                    float* __restrict__ out) {
    int x = blockIdx.x * blockDim.x + threadIdx.x;   // < NCH*BB*D4
    int d4 = x & (D4 - 1);
    int b = (x >> 8) & (BB - 1);
    int c = x >> 11;
    float4 dec = ((const float4*)decay)[d4];
    const float4* K4 = (const float4*)g_k;
    const float4* V4 = (const float4*)g_v;
    const float4* Q4 = (const float4*)g_q;
    float4* O4 = (float4*)out;
    size_t base = ((size_t)b * TT + (size_t)c * LCH) * D4 + d4;
    float4 mem = ((const float4*)g_carries)[((size_t)c * BB + b) * D4 + d4];
#pragma unroll 4
    for (int t = 0; t < LCH; t++) {
        size_t off = base + (size_t)t * D4;
        float4 kk = K4[off];
        float4 vv = V4[off];
        float4 qq = Q4[off];
        mem.x = fmaf(dec.x, mem.x, kk.x * vv.x);
        mem.y = fmaf(dec.y, mem.y, kk.y * vv.y);
        mem.z = fmaf(dec.z, mem.z, kk.z * vv.z);
        mem.w = fmaf(dec.w, mem.w, kk.w * vv.w);
        float4 o;
        o.x = qq.x * mem.x; o.y = qq.y * mem.y;
        o.z = qq.z * mem.z; o.w = qq.w * mem.w;
        O4[off] = o;
    }
}

// ---------------- launch -----------------------------------------------------
extern "C" void kernel_launch(void* const* d_in, const int* in_sizes, int n_in,
                              void* d_out, int out_size) {
    const float* x     = (const float*)d_in[0];
    const float* Wq    = (const float*)d_in[1];
    const float* bq    = (const float*)d_in[2];
    const float* Wk    = (const float*)d_in[3];
    const float* bk    = (const float*)d_in[4];
    const float* Wv    = (const float*)d_in[5];
    const float* bv    = (const float*)d_in[6];
    const float* decay = (const float*)d_in[7];
    float* out = (float*)d_out;

    float *q_p, *k_p, *v_p;
    __nv_bfloat16 *xhi_p, *xlo_p, *whi_p, *wlo_p;
    cudaGetSymbolAddress((void**)&q_p, g_q);
    cudaGetSymbolAddress((void**)&k_p, g_k);
    cudaGetSymbolAddress((void**)&v_p, g_v);
    cudaGetSymbolAddress((void**)&xhi_p, g_xhi);
    cudaGetSymbolAddress((void**)&xlo_p, g_xlo);
    cudaGetSymbolAddress((void**)&whi_p, g_whi);
    cudaGetSymbolAddress((void**)&wlo_p, g_wlo);

    const size_t WN = (size_t)DD * DD;
    const int XN4 = MT * DD / 4;           // 4M float4
    const int WN4 = (int)(WN / 4);         // 256K float4

    // hi/lo splits (grid-stride x4)
    split_kernel<<<XN4 / (256 * 4), 256>>>(x, xhi_p, xlo_p, XN4);
    split_kernel<<<WN4 / (256 * 4), 256>>>(Wq, whi_p + 0 * WN, wlo_p + 0 * WN, WN4);
    split_kernel<<<WN4 / (256 * 4), 256>>>(Wk, whi_p + 1 * WN, wlo_p + 1 * WN, WN4);
    split_kernel<<<WN4 / (256 * 4), 256>>>(Wv, whi_p + 2 * WN, wlo_p + 2 * WN, WN4);

    // fused QKV HMMA GEMM (single launch, N=3072)
    const int smem_bytes = NSTAGE * STAGE_B;   // 184320
    cudaFuncSetAttribute(gemm_qkv_kernel, cudaFuncAttributeMaxDynamicSharedMemorySize, smem_bytes);
    dim3 grid(3 * DD / 256, MT / 128);         // (12, 128) = 1536 CTAs
    gemm_qkv_kernel<<<grid, 256, smem_bytes>>>(xhi_p, xlo_p, whi_p, wlo_p,
                                               bq, bk, bv, q_p, k_p, v_p);

    // chunked scan (float4-vectorized)
    scan1_kernel<<<(NCH * BB * D4) / 256, 256>>>(decay);
    scan2_kernel<<<(BB * D4) / 256, 256>>>(decay);
    scan3_kernel<<<(NCH * BB * D4) / 256, 256>>>(decay, out);
}